// round 5
// baseline (speedup 1.0000x reference)
#include <cuda_runtime.h>
#include <cuda_bf16.h>
#include <math.h>

// Problem constants: N=50000, E=800000, D_IN=256, D_OUT=128, H=16
#define NMAX   50000
#define EMAX   800000
#define DOUT   128
#define DIN    256
#define HEDGE  16

#define MTILE  64      // nodes per CTA in proj_mma
#define P_A    264     // sA pitch in fp32
#define P_B    24      // sB pitch in bf16

// Scratch (device globals: allocation-free per harness rules)
__device__ float g_xp[NMAX * DOUT];            // x_proj, 25.6 MB
__device__ float g_s[NMAX];                    // per-node gate
__device__ __nv_bfloat16 g_Wt_hi[DOUT * DIN];  // W_in^T hi plane [n][k]
__device__ __nv_bfloat16 g_Wt_lo[DOUT * DIN];  // W_in^T lo plane [n][k]
// CSR scratch
__device__ int g_cnt[NMAX];
__device__ int g_off[NMAX + 1];
__device__ int g_cur[NMAX];
__device__ int g_perm[EMAX];
__device__ int g_bsum[64];
__device__ int g_boff[64];

// ---------------------------------------------------------------------------
__device__ __forceinline__ void split2(float f0, float f1, unsigned& hi, unsigned& lo) {
    asm("cvt.rn.bf16x2.f32 %0, %1, %2;" : "=r"(hi) : "f"(f1), "f"(f0));
    float h0 = __uint_as_float(hi << 16);
    float h1 = __uint_as_float(hi & 0xffff0000u);
    float r0 = f0 - h0;                   // exact (Sterbenz)
    float r1 = f1 - h1;
    asm("cvt.rn.bf16x2.f32 %0, %1, %2;" : "=r"(lo) : "f"(r1), "f"(r0));
}

__device__ __forceinline__ void mma_bf16(float c[4], const unsigned a[4],
                                         unsigned b0, unsigned b1) {
    asm("mma.sync.aligned.m16n8k16.row.col.f32.bf16.bf16.f32 "
        "{%0,%1,%2,%3}, {%4,%5,%6,%7}, {%8,%9}, {%0,%1,%2,%3};"
        : "+f"(c[0]), "+f"(c[1]), "+f"(c[2]), "+f"(c[3])
        : "r"(a[0]), "r"(a[1]), "r"(a[2]), "r"(a[3]), "r"(b0), "r"(b1));
}

// ---------------------------------------------------------------------------
// K0: prep — split/transpose W_in to bf16 hi/lo planes AND zero CSR counters
// ---------------------------------------------------------------------------
__global__ void prep_kernel(const float* __restrict__ Win, int n) {
    int i = blockIdx.x * blockDim.x + threadIdx.x;
    int stride = gridDim.x * blockDim.x;
    for (int j = i; j < DIN * DOUT; j += stride) {
        int k  = j >> 7;
        int nn = j & 127;
        float w = Win[j];
        __nv_bfloat16 h = __float2bfloat16_rn(w);
        __nv_bfloat16 l = __float2bfloat16_rn(w - __bfloat162float(h));
        g_Wt_hi[nn * DIN + k] = h;
        g_Wt_lo[nn * DIN + k] = l;
    }
    for (int j = i; j < n; j += stride) g_cnt[j] = 0;
}

// ---------------------------------------------------------------------------
// K1: x_proj = concat(x,state) @ W_in + b_in via bf16 MMA, 3-term split
// ---------------------------------------------------------------------------
__global__ void proj_mma_kernel(const float* __restrict__ x,
                                const float* __restrict__ state,
                                const float* __restrict__ bin,
                                int n) {
    extern __shared__ char smem[];
    float* sA = (float*)smem;
    __nv_bfloat16* sBhi = (__nv_bfloat16*)(smem + MTILE * P_A * 4);
    __nv_bfloat16* sBlo = sBhi + 128 * P_B;

    const int tid  = threadIdx.x;
    const int warp = tid >> 5;
    const int lane = tid & 31;
    const int gID  = lane >> 2;
    const int tID  = lane & 3;
    const int nb   = blockIdx.x * MTILE;

    for (int idx = tid; idx < MTILE * 64; idx += 128) {
        int node = idx >> 6;
        int kq   = idx & 63;
        int gn   = nb + node;
        float4 v = make_float4(0.f, 0.f, 0.f, 0.f);
        if (gn < n) v = (kq < 32) ? ((const float4*)x)[(size_t)gn * 32 + kq]
                                  : ((const float4*)state)[(size_t)gn * 32 + (kq - 32)];
        *(float4*)(sA + node * P_A + kq * 4) = v;
    }

    float c[16][4];
#pragma unroll
    for (int nt = 0; nt < 16; nt++)
#pragma unroll
        for (int j = 0; j < 4; j++) c[nt][j] = 0.0f;

    const int m0 = warp * 16;

    for (int kc = 0; kc < 16; kc++) {
        __syncthreads();
        {
            const uint4* sh = (const uint4*)(g_Wt_hi + tid * DIN + kc * 16);
            const uint4* sl = (const uint4*)(g_Wt_lo + tid * DIN + kc * 16);
            uint4 h0 = sh[0], h1 = sh[1];
            uint4 l0 = sl[0], l1 = sl[1];
            *(uint4*)(sBhi + tid * P_B)     = h0;
            *(uint4*)(sBhi + tid * P_B + 8) = h1;
            *(uint4*)(sBlo + tid * P_B)     = l0;
            *(uint4*)(sBlo + tid * P_B + 8) = l1;
        }
        __syncthreads();

        unsigned ah[4], al[4];
        const float* ar0 = sA + (m0 + gID) * P_A + kc * 16;
        const float* ar1 = sA + (m0 + gID + 8) * P_A + kc * 16;
        float2 p;
        p = *(const float2*)(ar0 + tID * 2);     split2(p.x, p.y, ah[0], al[0]);
        p = *(const float2*)(ar1 + tID * 2);     split2(p.x, p.y, ah[1], al[1]);
        p = *(const float2*)(ar0 + tID * 2 + 8); split2(p.x, p.y, ah[2], al[2]);
        p = *(const float2*)(ar1 + tID * 2 + 8); split2(p.x, p.y, ah[3], al[3]);

#pragma unroll
        for (int nt = 0; nt < 16; nt++) {
            const __nv_bfloat16* bh = sBhi + (nt * 8 + gID) * P_B + tID * 2;
            const __nv_bfloat16* bl = sBlo + (nt * 8 + gID) * P_B + tID * 2;
            unsigned bh0 = *(const unsigned*)(bh);
            unsigned bh1 = *(const unsigned*)(bh + 8);
            unsigned bl0 = *(const unsigned*)(bl);
            unsigned bl1 = *(const unsigned*)(bl + 8);
            mma_bf16(c[nt], ah, bh0, bh1);
            mma_bf16(c[nt], ah, bl0, bl1);
            mma_bf16(c[nt], al, bh0, bh1);
        }
    }

    int r0 = nb + m0 + gID;
    int r1 = r0 + 8;
#pragma unroll
    for (int nt = 0; nt < 16; nt++) {
        int col = nt * 8 + tID * 2;
        float2 bv = *(const float2*)(bin + col);
        if (r0 < n) {
            float2 o = make_float2(c[nt][0] + bv.x, c[nt][1] + bv.y);
            *(float2*)(g_xp + (size_t)r0 * 128 + col) = o;
        }
        if (r1 < n) {
            float2 o = make_float2(c[nt][2] + bv.x, c[nt][3] + bv.y);
            *(float2*)(g_xp + (size_t)r1 * 128 + col) = o;
        }
    }
}

// ---------------------------------------------------------------------------
// K2: per-node gate, 4 lanes per node (200k threads -> decent occupancy)
// ---------------------------------------------------------------------------
__global__ void gate_kernel(const float* __restrict__ W1,
                            const float* __restrict__ b1,
                            const float* __restrict__ W2,
                            const float* __restrict__ b2,
                            int n) {
    __shared__ float sW1[DIN / 2 * HEDGE];   // 128*16 = 8 KB
    __shared__ float sW2[HEDGE];
    __shared__ float sb1[HEDGE];
    for (int i = threadIdx.x; i < DOUT * HEDGE; i += blockDim.x) sW1[i] = W1[i];
    if (threadIdx.x < HEDGE) {
        sW2[threadIdx.x] = W2[threadIdx.x];
        sb1[threadIdx.x] = b1[threadIdx.x];
    }
    __syncthreads();

    int gt  = blockIdx.x * blockDim.x + threadIdx.x;
    int nid = gt >> 2;          // 4 lanes per node
    int sub = gt & 3;
    bool valid = (nid < n);

    float h[HEDGE];
#pragma unroll
    for (int j = 0; j < HEDGE; j++) h[j] = 0.0f;

    if (valid) {
        const float4* xp4 = (const float4*)(g_xp + (size_t)nid * 128 + sub * 32);
#pragma unroll
        for (int q = 0; q < 8; q++) {
            float4 v = xp4[q];
            float xs[4] = {v.x, v.y, v.z, v.w};
#pragma unroll
            for (int kk = 0; kk < 4; kk++) {
                const float* wr = sW1 + (sub * 32 + q * 4 + kk) * HEDGE;
#pragma unroll
                for (int j = 0; j < HEDGE; j++) h[j] += xs[kk] * wr[j];
            }
        }
    }

    // reduce across the 4-lane group
#pragma unroll
    for (int j = 0; j < HEDGE; j++) {
        h[j] += __shfl_xor_sync(0xffffffffu, h[j], 1);
        h[j] += __shfl_xor_sync(0xffffffffu, h[j], 2);
    }

    if (valid && sub == 0) {
        float z = b2[0];
#pragma unroll
        for (int j = 0; j < HEDGE; j++) {
            float hv = h[j] + sb1[j];
            hv = hv > 0.0f ? hv : 0.1f * hv;           // leaky_relu(0.1)
            z += hv * sW2[j];
        }
        float wd = 1.0f / (1.0f + expf(-z));
        float zz = 4.0f * (wd - 0.5f);
        g_s[nid] = log1pf(expf(zz));                   // softplus
    }
}

// ---------------------------------------------------------------------------
// CSR build: histogram -> exclusive scan (3 phases) -> scatter perm
// ---------------------------------------------------------------------------
__global__ void hist_kernel(const int* __restrict__ ei, int E, int n) {
    int e = blockIdx.x * blockDim.x + threadIdx.x;
    if (e >= E) return;
    int dst = ei[(size_t)E + e];
    if ((unsigned)dst < (unsigned)n) atomicAdd(&g_cnt[dst], 1);
}

__global__ void scan1_kernel(int n) {       // blockDim = 1024
    __shared__ int s[1024];
    int i = blockIdx.x * 1024 + threadIdx.x;
    int v = (i < n) ? g_cnt[i] : 0;
    s[threadIdx.x] = v;
    __syncthreads();
#pragma unroll
    for (int d = 1; d < 1024; d <<= 1) {
        int t = (threadIdx.x >= d) ? s[threadIdx.x - d] : 0;
        __syncthreads();
        s[threadIdx.x] += t;
        __syncthreads();
    }
    if (i < n) g_off[i] = s[threadIdx.x] - v;          // exclusive within block
    if (threadIdx.x == 1023) g_bsum[blockIdx.x] = s[1023];
}

__global__ void scan2_kernel(int nblk) {    // 1 block, blockDim = 64
    __shared__ int s[64];
    int v = (threadIdx.x < nblk) ? g_bsum[threadIdx.x] : 0;
    s[threadIdx.x] = v;
    __syncthreads();
#pragma unroll
    for (int d = 1; d < 64; d <<= 1) {
        int t = (threadIdx.x >= d) ? s[threadIdx.x - d] : 0;
        __syncthreads();
        s[threadIdx.x] += t;
        __syncthreads();
    }
    g_boff[threadIdx.x] = s[threadIdx.x] - v;          // exclusive
}

__global__ void scan3_kernel(int n) {
    int i = blockIdx.x * blockDim.x + threadIdx.x;
    if (i >= n) return;
    int o = g_off[i] + g_boff[i >> 10];
    g_off[i] = o;
    g_cur[i] = o;
    if (i == n - 1) g_off[n] = o + g_cnt[i];
}

__global__ void scatter_kernel(const int* __restrict__ ei, int E, int n) {
    int e = blockIdx.x * blockDim.x + threadIdx.x;
    if (e >= E) return;
    int dst = ei[(size_t)E + e];
    if ((unsigned)dst >= (unsigned)n) return;
    int pos = atomicAdd(&g_cur[dst], 1);
    g_perm[pos] = e;
}

// ---------------------------------------------------------------------------
// K3: pull aggregation + fused finalize. Warp per node, atomic-free.
// out[nid] = gelu( (sum_e w*xp[src]) / (sum_e |w| + eps) + xp[nid] )
// ---------------------------------------------------------------------------
__global__ void pull_kernel(const int* __restrict__ ei,
                            const float* __restrict__ ew,
                            float* __restrict__ out,
                            int E, int n) {
    int nid  = (blockIdx.x * blockDim.x + threadIdx.x) >> 5;
    int lane = threadIdx.x & 31;
    if (nid >= n) return;

    int beg = g_off[nid];
    int end = g_off[nid + 1];

    float4 acc = make_float4(0.f, 0.f, 0.f, 0.f);
    float  sw  = 0.0f;

    const float4* xp4 = (const float4*)g_xp;

    int j = beg;
    int e_next = (j < end) ? g_perm[j] : 0;
    for (; j < end; j++) {
        int e = e_next;
        if (j + 1 < end) e_next = g_perm[j + 1];
        int src = ei[e];
        float w = 0.0f;
        if ((unsigned)src < (unsigned)n) {
            w = ew[e] * g_s[src];
            w = fminf(fmaxf(w, 0.0f), 5.0f);
            float4 v = xp4[(size_t)src * 32 + lane];
            acc.x += w * v.x;
            acc.y += w * v.y;
            acc.z += w * v.z;
            acc.w += w * v.w;
            sw += fabsf(w);
        }
    }

    float inv = 1.0f / (sw + 1e-6f);
    float4 p  = xp4[(size_t)nid * 32 + lane];
    float v0 = acc.x * inv + p.x;
    float v1 = acc.y * inv + p.y;
    float v2 = acc.z * inv + p.z;
    float v3 = acc.w * inv + p.w;
    const float is2 = 0.70710678118654752f;
    float4 r;
    r.x = 0.5f * v0 * (1.0f + erff(v0 * is2));
    r.y = 0.5f * v1 * (1.0f + erff(v1 * is2));
    r.z = 0.5f * v2 * (1.0f + erff(v2 * is2));
    r.w = 0.5f * v3 * (1.0f + erff(v3 * is2));
    ((float4*)out)[(size_t)nid * 32 + lane] = r;
}

// ---------------------------------------------------------------------------
extern "C" void kernel_launch(void* const* d_in, const int* in_sizes, int n_in,
                              void* d_out, int out_size) {
    const float* x     = (const float*)d_in[0];
    const float* state = (const float*)d_in[1];
    const int*   ei    = (const int*)d_in[2];
    const float* ew    = (const float*)d_in[3];
    const float* Win   = (const float*)d_in[4];
    const float* bin   = (const float*)d_in[5];
    const float* W1    = (const float*)d_in[6];
    const float* b1    = (const float*)d_in[7];
    const float* W2    = (const float*)d_in[8];
    const float* b2    = (const float*)d_in[9];

    int n = in_sizes[0] / 128;     // 50000
    int E = in_sizes[3];           // 800000
    float* out = (float*)d_out;

    const int smem_proj = MTILE * P_A * 4 + 2 * 128 * P_B * 2;   // 79872 B
    static bool attr_set = false;
    if (!attr_set) {
        cudaFuncSetAttribute(proj_mma_kernel,
                             cudaFuncAttributeMaxDynamicSharedMemorySize, smem_proj);
        attr_set = true;
    }

    int nblk = (n + 1023) / 1024;

    prep_kernel<<<256, 256>>>(Win, n);
    proj_mma_kernel<<<(n + MTILE - 1) / MTILE, 128, smem_proj>>>(x, state, bin, n);
    gate_kernel<<<(n * 4 + 255) / 256, 256>>>(W1, b1, W2, b2, n);

    hist_kernel<<<(E + 255) / 256, 256>>>(ei, E, n);
    scan1_kernel<<<nblk, 1024>>>(n);
    scan2_kernel<<<1, 64>>>(nblk);
    scan3_kernel<<<(n + 255) / 256, 256>>>(n);
    scatter_kernel<<<(E + 255) / 256, 256>>>(ei, E, n);

    pull_kernel<<<(n * 32 + 255) / 256, 256>>>(ei, ew, out, E, n);
}

// round 6
// speedup vs baseline: 1.4413x; 1.4413x over previous
#include <cuda_runtime.h>
#include <cuda_bf16.h>
#include <math.h>

// Problem constants: N=50000, E=800000, D_IN=256, D_OUT=128, H=16
#define NMAX   50000
#define DOUT   128
#define DIN    256
#define HEDGE  16

#define MTILE  128     // nodes per CTA in proj_mma (8 warps x 16 rows)
#define P_A    264     // sA pitch in fp32
#define P_B    24      // sB pitch in bf16

// Scratch (device globals: allocation-free per harness rules)
__device__ float g_xp[NMAX * DOUT];            // x_proj, 25.6 MB (L2-resident)
__device__ float g_s[NMAX];                    // per-node gate
__device__ float g_deg[NMAX];                  // sum |w| per dst
__device__ __nv_bfloat16 g_Wt_hi[DOUT * DIN];  // W_in^T hi plane [n][k]
__device__ __nv_bfloat16 g_Wt_lo[DOUT * DIN];  // W_in^T lo plane [n][k]

// ---------------------------------------------------------------------------
__device__ __forceinline__ void split2(float f0, float f1, unsigned& hi, unsigned& lo) {
    asm("cvt.rn.bf16x2.f32 %0, %1, %2;" : "=r"(hi) : "f"(f1), "f"(f0));
    float h0 = __uint_as_float(hi << 16);
    float h1 = __uint_as_float(hi & 0xffff0000u);
    float r0 = f0 - h0;                   // exact (Sterbenz)
    float r1 = f1 - h1;
    asm("cvt.rn.bf16x2.f32 %0, %1, %2;" : "=r"(lo) : "f"(r1), "f"(r0));
}

__device__ __forceinline__ void mma_bf16(float c[4], const unsigned a[4],
                                         unsigned b0, unsigned b1) {
    asm("mma.sync.aligned.m16n8k16.row.col.f32.bf16.bf16.f32 "
        "{%0,%1,%2,%3}, {%4,%5,%6,%7}, {%8,%9}, {%0,%1,%2,%3};"
        : "+f"(c[0]), "+f"(c[1]), "+f"(c[2]), "+f"(c[3])
        : "r"(a[0]), "r"(a[1]), "r"(a[2]), "r"(a[3]), "r"(b0), "r"(b1));
}

// ---------------------------------------------------------------------------
// K0: prep — zero d_out + g_deg, split/transpose W_in to bf16 hi/lo planes
// ---------------------------------------------------------------------------
__global__ void prep_kernel(const float* __restrict__ Win,
                            float4* __restrict__ out4, int total4, int n) {
    int i = blockIdx.x * blockDim.x + threadIdx.x;
    int stride = gridDim.x * blockDim.x;
    float4 z = make_float4(0.f, 0.f, 0.f, 0.f);
    for (int j = i; j < total4; j += stride) out4[j] = z;
    for (int j = i; j < n; j += stride) g_deg[j] = 0.0f;
    for (int j = i; j < DIN * DOUT; j += stride) {
        int k  = j >> 7;
        int nn = j & 127;
        float w = Win[j];
        __nv_bfloat16 h = __float2bfloat16_rn(w);
        __nv_bfloat16 l = __float2bfloat16_rn(w - __bfloat162float(h));
        g_Wt_hi[nn * DIN + k] = h;
        g_Wt_lo[nn * DIN + k] = l;
    }
}

// ---------------------------------------------------------------------------
// K1: x_proj = concat(x,state) @ W_in + b_in via bf16 MMA (3-term split),
// with the edge-gate MLP FUSED into the epilogue (g_s written here).
// CTA: 128 nodes x 128 cols, 256 threads = 8 warps, warp tile 16x128.
// ---------------------------------------------------------------------------
__global__ void __launch_bounds__(256, 1)
proj_mma_kernel(const float* __restrict__ x,
                const float* __restrict__ state,
                const float* __restrict__ bin,
                const float* __restrict__ W1,
                const float* __restrict__ b1,
                const float* __restrict__ W2,
                const float* __restrict__ b2,
                int n) {
    extern __shared__ char smem[];
    float* sA = (float*)smem;                                       // [128][P_A]
    __nv_bfloat16* sBhi = (__nv_bfloat16*)(smem + MTILE * P_A * 4); // [128][P_B]
    __nv_bfloat16* sBlo = sBhi + 128 * P_B;
    float* sW1 = (float*)(sBlo + 128 * P_B);                        // [128][16]
    float* sW2 = sW1 + DOUT * HEDGE;                                // [16]
    float* sb1 = sW2 + HEDGE;                                       // [16]

    const int tid  = threadIdx.x;
    const int warp = tid >> 5;
    const int lane = tid & 31;
    const int gID  = lane >> 2;
    const int tID  = lane & 3;
    const int nb   = blockIdx.x * MTILE;

    // stage A tile (fp32 concat) + gate weights
    for (int idx = tid; idx < MTILE * 64; idx += 256) {
        int node = idx >> 6;
        int kq   = idx & 63;
        int gn   = nb + node;
        float4 v = make_float4(0.f, 0.f, 0.f, 0.f);
        if (gn < n) v = (kq < 32) ? ((const float4*)x)[(size_t)gn * 32 + kq]
                                  : ((const float4*)state)[(size_t)gn * 32 + (kq - 32)];
        *(float4*)(sA + node * P_A + kq * 4) = v;
    }
    for (int i = tid; i < DOUT * HEDGE; i += 256) sW1[i] = W1[i];
    if (tid < HEDGE) {
        sW2[tid] = W2[tid];
        sb1[tid] = b1[tid];
    }

    float c[16][4];
#pragma unroll
    for (int nt = 0; nt < 16; nt++)
#pragma unroll
        for (int j = 0; j < 4; j++) c[nt][j] = 0.0f;

    const int m0 = warp * 16;

    for (int kc = 0; kc < 16; kc++) {
        __syncthreads();
        // stage B chunk: 128 n-rows x 16 k, hi & lo. 2 threads per row.
        {
            int row  = tid >> 1;
            int half = tid & 1;
            const uint4* sh = (const uint4*)(g_Wt_hi + row * DIN + kc * 16 + half * 8);
            const uint4* sl = (const uint4*)(g_Wt_lo + row * DIN + kc * 16 + half * 8);
            uint4 h0 = *sh;
            uint4 l0 = *sl;
            *(uint4*)(sBhi + row * P_B + half * 8) = h0;
            *(uint4*)(sBlo + row * P_B + half * 8) = l0;
        }
        __syncthreads();

        unsigned ah[4], al[4];
        const float* ar0 = sA + (m0 + gID) * P_A + kc * 16;
        const float* ar1 = sA + (m0 + gID + 8) * P_A + kc * 16;
        float2 p;
        p = *(const float2*)(ar0 + tID * 2);     split2(p.x, p.y, ah[0], al[0]);
        p = *(const float2*)(ar1 + tID * 2);     split2(p.x, p.y, ah[1], al[1]);
        p = *(const float2*)(ar0 + tID * 2 + 8); split2(p.x, p.y, ah[2], al[2]);
        p = *(const float2*)(ar1 + tID * 2 + 8); split2(p.x, p.y, ah[3], al[3]);

#pragma unroll
        for (int nt = 0; nt < 16; nt++) {
            const __nv_bfloat16* bh = sBhi + (nt * 8 + gID) * P_B + tID * 2;
            const __nv_bfloat16* bl = sBlo + (nt * 8 + gID) * P_B + tID * 2;
            unsigned bh0 = *(const unsigned*)(bh);
            unsigned bh1 = *(const unsigned*)(bh + 8);
            unsigned bl0 = *(const unsigned*)(bl);
            unsigned bl1 = *(const unsigned*)(bl + 8);
            mma_bf16(c[nt], ah, bh0, bh1);
            mma_bf16(c[nt], ah, bl0, bl1);
            mma_bf16(c[nt], al, bh0, bh1);
        }
    }

    // epilogue: + bias, store x_proj, and fused gate MLP partials
    int r0 = nb + m0 + gID;
    int r1 = r0 + 8;

    float h0a[HEDGE], h1a[HEDGE];
#pragma unroll
    for (int j = 0; j < HEDGE; j++) { h0a[j] = 0.0f; h1a[j] = 0.0f; }

#pragma unroll
    for (int nt = 0; nt < 16; nt++) {
        int col = nt * 8 + tID * 2;
        float2 bv = *(const float2*)(bin + col);
        float o00 = c[nt][0] + bv.x, o01 = c[nt][1] + bv.y;   // row r0
        float o10 = c[nt][2] + bv.x, o11 = c[nt][3] + bv.y;   // row r1
        if (r0 < n) *(float2*)(g_xp + (size_t)r0 * 128 + col) = make_float2(o00, o01);
        if (r1 < n) *(float2*)(g_xp + (size_t)r1 * 128 + col) = make_float2(o10, o11);
        const float* w0 = sW1 + col * HEDGE;
        const float* w1 = sW1 + (col + 1) * HEDGE;
#pragma unroll
        for (int j = 0; j < HEDGE; j++) {
            h0a[j] += o00 * w0[j] + o01 * w1[j];
            h1a[j] += o10 * w0[j] + o11 * w1[j];
        }
    }

    // reduce gate partials over the 4 tID lanes of this row group
#pragma unroll
    for (int j = 0; j < HEDGE; j++) {
        h0a[j] += __shfl_xor_sync(0xffffffffu, h0a[j], 1);
        h0a[j] += __shfl_xor_sync(0xffffffffu, h0a[j], 2);
        h1a[j] += __shfl_xor_sync(0xffffffffu, h1a[j], 1);
        h1a[j] += __shfl_xor_sync(0xffffffffu, h1a[j], 2);
    }

    if (tID == 0) {
        float bias2 = b2[0];
        if (r0 < n) {
            float z = bias2;
#pragma unroll
            for (int j = 0; j < HEDGE; j++) {
                float hv = h0a[j] + sb1[j];
                hv = hv > 0.0f ? hv : 0.1f * hv;       // leaky_relu(0.1)
                z += hv * sW2[j];
            }
            float wd = 1.0f / (1.0f + expf(-z));
            g_s[r0] = log1pf(expf(4.0f * (wd - 0.5f)));
        }
        if (r1 < n) {
            float z = bias2;
#pragma unroll
            for (int j = 0; j < HEDGE; j++) {
                float hv = h1a[j] + sb1[j];
                hv = hv > 0.0f ? hv : 0.1f * hv;
                z += hv * sW2[j];
            }
            float wd = 1.0f / (1.0f + expf(-z));
            g_s[r1] = log1pf(expf(4.0f * (wd - 0.5f)));
        }
    }
}

// ---------------------------------------------------------------------------
// K2: edge scatter (push). One warp per edge; lane l -> cols [4l, 4l+4).
// red.global.add.v4.f32 — at the L2 traffic floor (~112us), proven R3/R4.
// ---------------------------------------------------------------------------
__global__ void edge_kernel(const int* __restrict__ ei,
                            const float* __restrict__ ew,
                            float* __restrict__ out,
                            int E, int n) {
    int wid  = (blockIdx.x * blockDim.x + threadIdx.x) >> 5;
    int lane = threadIdx.x & 31;
    if (wid >= E) return;

    int src = ei[wid];
    int dst = ei[(size_t)E + wid];
    if ((unsigned)src >= (unsigned)n || (unsigned)dst >= (unsigned)n) return;

    float w = ew[wid] * g_s[src];
    w = fminf(fmaxf(w, 0.0f), 5.0f);                   // clip to [0, EW_MAX]

    float4 v = *(const float4*)(g_xp + (size_t)src * 128 + lane * 4);
    float* o = out + (size_t)dst * 128 + lane * 4;
    asm volatile("red.global.add.v4.f32 [%0], {%1, %2, %3, %4};"
                 :: "l"(o), "f"(w * v.x), "f"(w * v.y), "f"(w * v.z), "f"(w * v.w)
                 : "memory");
    if (lane == 0) atomicAdd(&g_deg[dst], fabsf(w));
}

// ---------------------------------------------------------------------------
// K3: finalize: gelu(out/(deg+eps) + x_proj), float4-vectorized
// ---------------------------------------------------------------------------
__global__ void finalize_kernel(float4* __restrict__ out4, int n) {
    int i = blockIdx.x * blockDim.x + threadIdx.x;
    int total4 = n * 32;
    if (i >= total4) return;
    int nid = i >> 5;
    float inv = 1.0f / (g_deg[nid] + 1e-6f);
    float4 a = out4[i];
    float4 p = ((const float4*)g_xp)[i];
    float v0 = a.x * inv + p.x;
    float v1 = a.y * inv + p.y;
    float v2 = a.z * inv + p.z;
    float v3 = a.w * inv + p.w;
    const float is2 = 0.70710678118654752f;
    float4 r;
    r.x = 0.5f * v0 * (1.0f + erff(v0 * is2));
    r.y = 0.5f * v1 * (1.0f + erff(v1 * is2));
    r.z = 0.5f * v2 * (1.0f + erff(v2 * is2));
    r.w = 0.5f * v3 * (1.0f + erff(v3 * is2));
    out4[i] = r;
}

// ---------------------------------------------------------------------------
extern "C" void kernel_launch(void* const* d_in, const int* in_sizes, int n_in,
                              void* d_out, int out_size) {
    const float* x     = (const float*)d_in[0];
    const float* state = (const float*)d_in[1];
    const int*   ei    = (const int*)d_in[2];
    const float* ew    = (const float*)d_in[3];
    const float* Win   = (const float*)d_in[4];
    const float* bin   = (const float*)d_in[5];
    const float* W1    = (const float*)d_in[6];
    const float* b1    = (const float*)d_in[7];
    const float* W2    = (const float*)d_in[8];
    const float* b2    = (const float*)d_in[9];

    int n = in_sizes[0] / 128;     // 50000
    int E = in_sizes[3];           // 800000
    float* out = (float*)d_out;

    // smem: A tile + B chunks (hi/lo) + gate weights
    const int smem_proj = MTILE * P_A * 4 + 2 * 128 * P_B * 2
                        + (DOUT * HEDGE + 2 * HEDGE) * 4;   // ~156 KB
    static bool attr_set = false;
    if (!attr_set) {
        cudaFuncSetAttribute(proj_mma_kernel,
                             cudaFuncAttributeMaxDynamicSharedMemorySize, smem_proj);
        attr_set = true;
    }

    prep_kernel<<<2048, 256>>>(Win, (float4*)out, out_size / 4, n);
    proj_mma_kernel<<<(n + MTILE - 1) / MTILE, 256, smem_proj>>>(
        x, state, bin, W1, b1, W2, b2, n);

    int edge_blocks = (int)(((long long)E * 32 + 255) / 256);
    edge_kernel<<<edge_blocks, 256>>>(ei, ew, out, E, n);

    finalize_kernel<<<(n * 32 + 255) / 256, 256>>>((float4*)out, n);
}

// round 7
// speedup vs baseline: 1.5936x; 1.1057x over previous
#include <cuda_runtime.h>
#include <cuda_bf16.h>
#include <math.h>

// Problem constants: N=50000, E=800000, D_IN=256, D_OUT=128, H=16
#define NMAX   50000
#define DOUT   128
#define DIN    256
#define HEDGE  16

#define MTILE  128     // nodes per CTA in proj_mma
#define P_A    264     // sA pitch in fp32
#define P_B    24      // sB pitch in bf16

// Scratch (device globals: allocation-free per harness rules)
__device__ float g_xp[NMAX * DOUT];            // x_proj, 25.6 MB (L2-resident)
__device__ float g_s[NMAX];                    // per-node gate
__device__ float g_deg[NMAX];                  // sum |w| per dst
__device__ __nv_bfloat16 g_Wt_hi[DOUT * DIN];  // W_in^T hi plane [n][k]
__device__ __nv_bfloat16 g_Wt_lo[DOUT * DIN];  // W_in^T lo plane [n][k]

// ---------------------------------------------------------------------------
__device__ __forceinline__ void split2(float f0, float f1, unsigned& hi, unsigned& lo) {
    asm("cvt.rn.bf16x2.f32 %0, %1, %2;" : "=r"(hi) : "f"(f1), "f"(f0));
    float h0 = __uint_as_float(hi << 16);
    float h1 = __uint_as_float(hi & 0xffff0000u);
    float r0 = f0 - h0;                   // exact (Sterbenz)
    float r1 = f1 - h1;
    asm("cvt.rn.bf16x2.f32 %0, %1, %2;" : "=r"(lo) : "f"(r1), "f"(r0));
}

__device__ __forceinline__ void mma_bf16(float c[4], const unsigned a[4],
                                         unsigned b0, unsigned b1) {
    asm("mma.sync.aligned.m16n8k16.row.col.f32.bf16.bf16.f32 "
        "{%0,%1,%2,%3}, {%4,%5,%6,%7}, {%8,%9}, {%0,%1,%2,%3};"
        : "+f"(c[0]), "+f"(c[1]), "+f"(c[2]), "+f"(c[3])
        : "r"(a[0]), "r"(a[1]), "r"(a[2]), "r"(a[3]), "r"(b0), "r"(b1));
}

// ---------------------------------------------------------------------------
// K0: prep — zero d_out + g_deg, split/transpose W_in to bf16 hi/lo planes
// ---------------------------------------------------------------------------
__global__ void prep_kernel(const float* __restrict__ Win,
                            float4* __restrict__ out4, int total4, int n) {
    int i = blockIdx.x * blockDim.x + threadIdx.x;
    int stride = gridDim.x * blockDim.x;
    float4 z = make_float4(0.f, 0.f, 0.f, 0.f);
    for (int j = i; j < total4; j += stride) out4[j] = z;
    for (int j = i; j < n; j += stride) g_deg[j] = 0.0f;
    for (int j = i; j < DIN * DOUT; j += stride) {
        int k  = j >> 7;
        int nn = j & 127;
        float w = Win[j];
        __nv_bfloat16 h = __float2bfloat16_rn(w);
        __nv_bfloat16 l = __float2bfloat16_rn(w - __bfloat162float(h));
        g_Wt_hi[nn * DIN + k] = h;
        g_Wt_lo[nn * DIN + k] = l;
    }
}

// ---------------------------------------------------------------------------
// K1: x_proj = concat(x,state) @ W_in + b_in via bf16 MMA (3-term split),
// gate MLP fused. 512 threads = 16 warps: warp = (rowgrp 0..7, colhalf 0..1),
// warp tile 16 rows x 64 cols. B chunks register-prefetched (latency hidden).
// ---------------------------------------------------------------------------
__global__ void __launch_bounds__(512, 1)
proj_mma_kernel(const float* __restrict__ x,
                const float* __restrict__ state,
                const float* __restrict__ bin,
                const float* __restrict__ W1,
                const float* __restrict__ b1,
                const float* __restrict__ W2,
                const float* __restrict__ b2,
                int n) {
    extern __shared__ char smem[];
    float* sA = (float*)smem;                                       // [128][P_A]
    __nv_bfloat16* sBhi = (__nv_bfloat16*)(smem + MTILE * P_A * 4); // [128][P_B]
    __nv_bfloat16* sBlo = sBhi + 128 * P_B;
    float* sW1 = (float*)(sBlo + 128 * P_B);                        // [128][16]
    float* sW2 = sW1 + DOUT * HEDGE;
    float* sb1 = sW2 + HEDGE;
    // gate partials aliased onto dead A tile (valid only after post-loop sync)
    float* sH0 = sA;                 // [128][16]
    float* sH1 = sA + MTILE * HEDGE; // [128][16]

    const int tid     = threadIdx.x;
    const int warp    = tid >> 5;
    const int lane    = tid & 31;
    const int gID     = lane >> 2;
    const int tID     = lane & 3;
    const int rowgrp  = warp & 7;
    const int colhalf = warp >> 3;
    const int nb      = blockIdx.x * MTILE;
    const int m0      = rowgrp * 16;
    const int cbase   = colhalf * 64;

    // stage A tile (fp32 concat) + gate weights
    for (int idx = tid; idx < MTILE * 64; idx += 512) {
        int node = idx >> 6;
        int kq   = idx & 63;
        int gn   = nb + node;
        float4 v = make_float4(0.f, 0.f, 0.f, 0.f);
        if (gn < n) v = (kq < 32) ? ((const float4*)x)[(size_t)gn * 32 + kq]
                                  : ((const float4*)state)[(size_t)gn * 32 + (kq - 32)];
        *(float4*)(sA + node * P_A + kq * 4) = v;
    }
    for (int i = tid; i < DOUT * HEDGE; i += 512) sW1[i] = W1[i];
    if (tid < HEDGE) {
        sW2[tid] = W2[tid];
        sb1[tid] = b1[tid];
    }

    // B prefetch setup: 512 threads cover 2 planes x 128 rows x 2 halves
    const int bplane = tid >> 8;          // 0 = hi, 1 = lo
    const int brow   = (tid >> 1) & 127;
    const int bhalf  = tid & 1;
    const __nv_bfloat16* gW = bplane ? g_Wt_lo : g_Wt_hi;
    __nv_bfloat16* sBdst = (bplane ? sBlo : sBhi) + brow * P_B + bhalf * 8;
    const __nv_bfloat16* gsrc = gW + brow * DIN + bhalf * 8;
    uint4 pf = *(const uint4*)(gsrc);     // chunk 0

    float c[8][4];
#pragma unroll
    for (int nt = 0; nt < 8; nt++)
#pragma unroll
        for (int j = 0; j < 4; j++) c[nt][j] = 0.0f;

    for (int kc = 0; kc < 16; kc++) {
        __syncthreads();                   // consumers of previous chunk done
        *(uint4*)sBdst = pf;
        if (kc < 15) pf = *(const uint4*)(gsrc + (kc + 1) * 16);   // overlap w/ compute
        __syncthreads();

        unsigned ah[4], al[4];
        const float* ar0 = sA + (m0 + gID) * P_A + kc * 16;
        const float* ar1 = sA + (m0 + gID + 8) * P_A + kc * 16;
        float2 p;
        p = *(const float2*)(ar0 + tID * 2);     split2(p.x, p.y, ah[0], al[0]);
        p = *(const float2*)(ar1 + tID * 2);     split2(p.x, p.y, ah[1], al[1]);
        p = *(const float2*)(ar0 + tID * 2 + 8); split2(p.x, p.y, ah[2], al[2]);
        p = *(const float2*)(ar1 + tID * 2 + 8); split2(p.x, p.y, ah[3], al[3]);

#pragma unroll
        for (int nt = 0; nt < 8; nt++) {
            const __nv_bfloat16* bh = sBhi + (cbase + nt * 8 + gID) * P_B + tID * 2;
            const __nv_bfloat16* bl = sBlo + (cbase + nt * 8 + gID) * P_B + tID * 2;
            unsigned bh0 = *(const unsigned*)(bh);
            unsigned bh1 = *(const unsigned*)(bh + 8);
            unsigned bl0 = *(const unsigned*)(bl);
            unsigned bl1 = *(const unsigned*)(bl + 8);
            mma_bf16(c[nt], ah, bh0, bh1);
            mma_bf16(c[nt], ah, bl0, bl1);
            mma_bf16(c[nt], al, bh0, bh1);
        }
    }

    // epilogue: + bias, store x_proj, gate partials over this warp's 64 cols
    int r0 = nb + m0 + gID;
    int r1 = r0 + 8;

    float h0a[HEDGE], h1a[HEDGE];
#pragma unroll
    for (int j = 0; j < HEDGE; j++) { h0a[j] = 0.0f; h1a[j] = 0.0f; }

#pragma unroll
    for (int nt = 0; nt < 8; nt++) {
        int col = cbase + nt * 8 + tID * 2;
        float2 bv = *(const float2*)(bin + col);
        float o00 = c[nt][0] + bv.x, o01 = c[nt][1] + bv.y;   // row r0
        float o10 = c[nt][2] + bv.x, o11 = c[nt][3] + bv.y;   // row r1
        if (r0 < n) *(float2*)(g_xp + (size_t)r0 * 128 + col) = make_float2(o00, o01);
        if (r1 < n) *(float2*)(g_xp + (size_t)r1 * 128 + col) = make_float2(o10, o11);
        const float* w0 = sW1 + col * HEDGE;
        const float* w1 = sW1 + (col + 1) * HEDGE;
#pragma unroll
        for (int j = 0; j < HEDGE; j++) {
            h0a[j] += o00 * w0[j] + o01 * w1[j];
            h1a[j] += o10 * w0[j] + o11 * w1[j];
        }
    }

    // reduce over the 4 tID lanes
#pragma unroll
    for (int j = 0; j < HEDGE; j++) {
        h0a[j] += __shfl_xor_sync(0xffffffffu, h0a[j], 1);
        h0a[j] += __shfl_xor_sync(0xffffffffu, h0a[j], 2);
        h1a[j] += __shfl_xor_sync(0xffffffffu, h1a[j], 1);
        h1a[j] += __shfl_xor_sync(0xffffffffu, h1a[j], 2);
    }

    __syncthreads();   // everyone done reading sA -> safe to alias sH onto it

    if (tID == 0) {
        float* dst = (colhalf ? sH1 : sH0);
#pragma unroll
        for (int j = 0; j < HEDGE; j++) {
            dst[(m0 + gID) * HEDGE + j]     = h0a[j];
            dst[(m0 + gID + 8) * HEDGE + j] = h1a[j];
        }
    }
    __syncthreads();

    // gate finalize: one thread per row
    if (tid < MTILE) {
        int gr = nb + tid;
        if (gr < n) {
            float z = b2[0];
#pragma unroll
            for (int j = 0; j < HEDGE; j++) {
                float hv = sH0[tid * HEDGE + j] + sH1[tid * HEDGE + j] + sb1[j];
                hv = hv > 0.0f ? hv : 0.1f * hv;       // leaky_relu(0.1)
                z += hv * sW2[j];
            }
            float wd = 1.0f / (1.0f + expf(-z));
            g_s[gr] = log1pf(expf(4.0f * (wd - 0.5f)));
        }
    }
}

// ---------------------------------------------------------------------------
// K2: edge scatter (push). One warp per edge; lane l -> cols [4l, 4l+4).
// red.global.add.v4.f32 — at the L2 traffic floor (~112us). Unchanged.
// ---------------------------------------------------------------------------
__global__ void edge_kernel(const int* __restrict__ ei,
                            const float* __restrict__ ew,
                            float* __restrict__ out,
                            int E, int n) {
    int wid  = (blockIdx.x * blockDim.x + threadIdx.x) >> 5;
    int lane = threadIdx.x & 31;
    if (wid >= E) return;

    int src = ei[wid];
    int dst = ei[(size_t)E + wid];
    if ((unsigned)src >= (unsigned)n || (unsigned)dst >= (unsigned)n) return;

    float w = ew[wid] * g_s[src];
    w = fminf(fmaxf(w, 0.0f), 5.0f);                   // clip to [0, EW_MAX]

    float4 v = *(const float4*)(g_xp + (size_t)src * 128 + lane * 4);
    float* o = out + (size_t)dst * 128 + lane * 4;
    asm volatile("red.global.add.v4.f32 [%0], {%1, %2, %3, %4};"
                 :: "l"(o), "f"(w * v.x), "f"(w * v.y), "f"(w * v.z), "f"(w * v.w)
                 : "memory");
    if (lane == 0) atomicAdd(&g_deg[dst], fabsf(w));
}

// ---------------------------------------------------------------------------
// K3: finalize: gelu(out/(deg+eps) + x_proj), float4-vectorized
// ---------------------------------------------------------------------------
__global__ void finalize_kernel(float4* __restrict__ out4, int n) {
    int i = blockIdx.x * blockDim.x + threadIdx.x;
    int total4 = n * 32;
    if (i >= total4) return;
    int nid = i >> 5;
    float inv = 1.0f / (g_deg[nid] + 1e-6f);
    float4 a = out4[i];
    float4 p = ((const float4*)g_xp)[i];
    float v0 = a.x * inv + p.x;
    float v1 = a.y * inv + p.y;
    float v2 = a.z * inv + p.z;
    float v3 = a.w * inv + p.w;
    const float is2 = 0.70710678118654752f;
    float4 r;
    r.x = 0.5f * v0 * (1.0f + erff(v0 * is2));
    r.y = 0.5f * v1 * (1.0f + erff(v1 * is2));
    r.z = 0.5f * v2 * (1.0f + erff(v2 * is2));
    r.w = 0.5f * v3 * (1.0f + erff(v3 * is2));
    out4[i] = r;
}

// ---------------------------------------------------------------------------
extern "C" void kernel_launch(void* const* d_in, const int* in_sizes, int n_in,
                              void* d_out, int out_size) {
    const float* x     = (const float*)d_in[0];
    const float* state = (const float*)d_in[1];
    const int*   ei    = (const int*)d_in[2];
    const float* ew    = (const float*)d_in[3];
    const float* Win   = (const float*)d_in[4];
    const float* bin   = (const float*)d_in[5];
    const float* W1    = (const float*)d_in[6];
    const float* b1    = (const float*)d_in[7];
    const float* W2    = (const float*)d_in[8];
    const float* b2    = (const float*)d_in[9];

    int n = in_sizes[0] / 128;     // 50000
    int E = in_sizes[3];           // 800000
    float* out = (float*)d_out;

    const int smem_proj = MTILE * P_A * 4 + 2 * 128 * P_B * 2
                        + (DOUT * HEDGE + 2 * HEDGE) * 4;   // ~156 KB
    static bool attr_set = false;
    if (!attr_set) {
        cudaFuncSetAttribute(proj_mma_kernel,
                             cudaFuncAttributeMaxDynamicSharedMemorySize, smem_proj);
        attr_set = true;
    }

    prep_kernel<<<2048, 256>>>(Win, (float4*)out, out_size / 4, n);
    proj_mma_kernel<<<(n + MTILE - 1) / MTILE, 512, smem_proj>>>(
        x, state, bin, W1, b1, W2, b2, n);

    int edge_blocks = (int)(((long long)E * 32 + 255) / 256);
    edge_kernel<<<edge_blocks, 256>>>(ei, ew, out, E, n);

    finalize_kernel<<<(n * 32 + 255) / 256, 256>>>((float4*)out, n);
}

// round 9
// speedup vs baseline: 1.6227x; 1.0183x over previous
#include <cuda_runtime.h>
#include <cuda_bf16.h>
#include <math.h>

// Problem constants: N=50000, E=800000, D_IN=256, D_OUT=128, H=16
#define NMAX   50000
#define DOUT   128
#define DIN    256
#define HEDGE  16

#define MTILE  128     // nodes per CTA in proj_mma
#define PAW    132     // A plane pitch in 32-bit words (264 bf16)
#define P_B    24      // B chunk pitch in bf16

// Scratch (device globals: allocation-free per harness rules)
__device__ float g_xp[NMAX * DOUT];            // x_proj, 25.6 MB (L2-resident)
__device__ float g_s[NMAX];                    // per-node gate
__device__ float g_deg[NMAX];                  // sum |w| per dst
__device__ __nv_bfloat16 g_Wt_hi[DOUT * DIN];  // W_in^T hi plane [n][k]
__device__ __nv_bfloat16 g_Wt_lo[DOUT * DIN];  // W_in^T lo plane [n][k]

// ---------------------------------------------------------------------------
__device__ __forceinline__ void split2(float f0, float f1, unsigned& hi, unsigned& lo) {
    asm("cvt.rn.bf16x2.f32 %0, %1, %2;" : "=r"(hi) : "f"(f1), "f"(f0));
    float h0 = __uint_as_float(hi << 16);
    float h1 = __uint_as_float(hi & 0xffff0000u);
    float r0 = f0 - h0;                   // exact (Sterbenz)
    float r1 = f1 - h1;
    asm("cvt.rn.bf16x2.f32 %0, %1, %2;" : "=r"(lo) : "f"(r1), "f"(r0));
}

__device__ __forceinline__ void mma_bf16(float c[4], const unsigned a[4],
                                         unsigned b0, unsigned b1) {
    asm("mma.sync.aligned.m16n8k16.row.col.f32.bf16.bf16.f32 "
        "{%0,%1,%2,%3}, {%4,%5,%6,%7}, {%8,%9}, {%0,%1,%2,%3};"
        : "+f"(c[0]), "+f"(c[1]), "+f"(c[2]), "+f"(c[3])
        : "r"(a[0]), "r"(a[1]), "r"(a[2]), "r"(a[3]), "r"(b0), "r"(b1));
}

// ---------------------------------------------------------------------------
// SMEM layout (bytes) for proj
// ---------------------------------------------------------------------------
#define SM_AHI   0                         // 128 x PAW words bf16x2 = 67584 B
#define SM_ALO   67584                     // 67584 B
#define SM_B0H   135168                    // B chunk buf0 hi: 6144 B
#define SM_B0L   141312
#define SM_B1H   147456
#define SM_B1L   153600
#define SM_W1    159744                    // 128x16 fp32 = 8192 B
#define SM_W2    167936                    // 64 B
#define SM_B1V   168000                    // 64 B
#define SM_BIN   168064                    // 512 B
#define SM_TOTAL 168576

// ---------------------------------------------------------------------------
// K0: prep — zero d_out + g_deg, split/transpose W_in to bf16 hi/lo planes
// ---------------------------------------------------------------------------
__global__ void prep_kernel(const float* __restrict__ Win,
                            float4* __restrict__ out4, int total4, int n) {
    int i = blockIdx.x * blockDim.x + threadIdx.x;
    int stride = gridDim.x * blockDim.x;
    float4 z = make_float4(0.f, 0.f, 0.f, 0.f);
    for (int j = i; j < total4; j += stride) out4[j] = z;
    for (int j = i; j < n; j += stride) g_deg[j] = 0.0f;
    for (int j = i; j < DIN * DOUT; j += stride) {
        int k  = j >> 7;
        int nn = j & 127;
        float w = Win[j];
        __nv_bfloat16 h = __float2bfloat16_rn(w);
        __nv_bfloat16 l = __float2bfloat16_rn(w - __bfloat162float(h));
        g_Wt_hi[nn * DIN + k] = h;
        g_Wt_lo[nn * DIN + k] = l;
    }
}

// ---------------------------------------------------------------------------
// K1: x_proj = concat(x,state) @ W_in + b_in via bf16 mma.sync (3-term split),
// gate MLP fused. 512 threads = 16 warps: warp = (rowgrp 0..7, colhalf 0..1).
// A pre-split to smem bf16 planes ONCE; B double-buffered, 1 sync per chunk.
// ---------------------------------------------------------------------------
__global__ void __launch_bounds__(512, 1)
proj_mma_kernel(const float* __restrict__ x,
                const float* __restrict__ state,
                const float* __restrict__ bin,
                const float* __restrict__ W1,
                const float* __restrict__ b1,
                const float* __restrict__ W2,
                const float* __restrict__ b2,
                int n) {
    extern __shared__ char smem[];
    unsigned* sAhi = (unsigned*)(smem + SM_AHI);   // [128][PAW] bf16x2 words
    unsigned* sAlo = (unsigned*)(smem + SM_ALO);
    float* sW1 = (float*)(smem + SM_W1);
    float* sW2 = (float*)(smem + SM_W2);
    float* sb1 = (float*)(smem + SM_B1V);
    float* sBN = (float*)(smem + SM_BIN);
    // gate partials aliased onto dead A planes after the mainloop
    float* sH0 = (float*)(smem + SM_AHI);          // [128][16]
    float* sH1 = sH0 + MTILE * HEDGE;

    const int tid     = threadIdx.x;
    const int warp    = tid >> 5;
    const int lane    = tid & 31;
    const int gID     = lane >> 2;
    const int tID     = lane & 3;
    const int rowgrp  = warp & 7;
    const int colhalf = warp >> 3;
    const int nb      = blockIdx.x * MTILE;
    const int m0      = rowgrp * 16;
    const int cbase   = colhalf * 64;

    // ---- stage A: split fp32 -> bf16 hi/lo planes, each element ONCE ----
    {
        int r = tid >> 2;          // row 0..127
        int q = tid & 3;           // quarter: 0,1 = x; 2,3 = state
        int gn = nb + r;
        bool valid = (gn < n);
        const float4* src = (q < 2)
            ? (const float4*)(x + (size_t)(valid ? gn : 0) * 128) + (q & 1) * 16
            : (const float4*)(state + (size_t)(valid ? gn : 0) * 128) + (q & 1) * 16;
        unsigned base = r * PAW + q * 32;
#pragma unroll
        for (int j = 0; j < 16; j++) {
            float4 v = valid ? src[j] : make_float4(0.f, 0.f, 0.f, 0.f);
            unsigned h0, l0, h1, l1;
            split2(v.x, v.y, h0, l0);
            split2(v.z, v.w, h1, l1);
            sAhi[base + 2 * j]     = h0;
            sAhi[base + 2 * j + 1] = h1;
            sAlo[base + 2 * j]     = l0;
            sAlo[base + 2 * j + 1] = l1;
        }
    }
    // gate weights + bias
    for (int i = tid; i < DOUT * HEDGE; i += 512) sW1[i] = W1[i];
    if (tid < HEDGE) {
        sW2[tid] = W2[tid];
        sb1[tid] = b1[tid];
    }
    if (tid >= 512 - DOUT) sBN[tid - (512 - DOUT)] = bin[tid - (512 - DOUT)];

    // ---- B staging setup: 512 threads = 2 planes x 128 rows x 2 halves ----
    const int bplane = tid >> 8;          // 0 = hi, 1 = lo
    const int brow   = (tid >> 1) & 127;
    const int bhalf  = tid & 1;
    const __nv_bfloat16* gsrc =
        (bplane ? g_Wt_lo : g_Wt_hi) + brow * DIN + bhalf * 8;
    char* sBd0 = smem + (bplane ? SM_B0L : SM_B0H) + brow * (P_B * 2) + bhalf * 16;
    char* sBd1 = smem + (bplane ? SM_B1L : SM_B1H) + brow * (P_B * 2) + bhalf * 16;

    // chunk 0 into buf0, prefetch chunk 1
    *(uint4*)sBd0 = *(const uint4*)(gsrc);
    uint4 pf = *(const uint4*)(gsrc + 16);
    __syncthreads();

    float c[8][4];
#pragma unroll
    for (int nt = 0; nt < 8; nt++)
#pragma unroll
        for (int j = 0; j < 4; j++) c[nt][j] = 0.0f;

    for (int kc = 0; kc < 16; kc++) {
        // store prefetched chunk kc+1 into the other buffer (its last readers
        // finished at the sync ending iteration kc-1), prefetch kc+2
        if (kc < 15) {
            *(uint4*)(((kc & 1) == 0) ? sBd1 : sBd0) = pf;
            if (kc < 14) pf = *(const uint4*)(gsrc + (kc + 2) * 16);
        }

        // A fragments: 8 conflict-free LDS.32 (pre-split bf16x2)
        unsigned ah[4], al[4];
        {
            unsigned w0 = (m0 + gID) * PAW + kc * 8 + tID;
            unsigned w1 = w0 + 8 * PAW;
            ah[0] = sAhi[w0];     al[0] = sAlo[w0];
            ah[1] = sAhi[w1];     al[1] = sAlo[w1];
            ah[2] = sAhi[w0 + 4]; al[2] = sAlo[w0 + 4];
            ah[3] = sAhi[w1 + 4]; al[3] = sAlo[w1 + 4];
        }

        const __nv_bfloat16* bH = (const __nv_bfloat16*)
            (smem + ((kc & 1) ? SM_B1H : SM_B0H));
        const __nv_bfloat16* bL = (const __nv_bfloat16*)
            (smem + ((kc & 1) ? SM_B1L : SM_B0L));

#pragma unroll
        for (int nt = 0; nt < 8; nt++) {
            const __nv_bfloat16* ph = bH + (cbase + nt * 8 + gID) * P_B + tID * 2;
            const __nv_bfloat16* pl = bL + (cbase + nt * 8 + gID) * P_B + tID * 2;
            unsigned bh0 = *(const unsigned*)(ph);
            unsigned bh1 = *(const unsigned*)(ph + 8);
            unsigned bl0 = *(const unsigned*)(pl);
            unsigned bl1 = *(const unsigned*)(pl + 8);
            mma_bf16(c[nt], ah, bh0, bh1);
            mma_bf16(c[nt], ah, bl0, bl1);
            mma_bf16(c[nt], al, bh0, bh1);
        }
        __syncthreads();
    }

    // ---- epilogue: + bias, store x_proj, fused gate partials ----
    int r0 = nb + m0 + gID;
    int r1 = r0 + 8;

    float h0a[HEDGE], h1a[HEDGE];
#pragma unroll
    for (int j = 0; j < HEDGE; j++) { h0a[j] = 0.0f; h1a[j] = 0.0f; }

#pragma unroll
    for (int nt = 0; nt < 8; nt++) {
        int col = cbase + nt * 8 + tID * 2;
        float2 bv = make_float2(sBN[col], sBN[col + 1]);
        float o00 = c[nt][0] + bv.x, o01 = c[nt][1] + bv.y;   // row r0
        float o10 = c[nt][2] + bv.x, o11 = c[nt][3] + bv.y;   // row r1
        if (r0 < n) *(float2*)(g_xp + (size_t)r0 * 128 + col) = make_float2(o00, o01);
        if (r1 < n) *(float2*)(g_xp + (size_t)r1 * 128 + col) = make_float2(o10, o11);
        const float* w0 = sW1 + col * HEDGE;
        const float* w1 = sW1 + (col + 1) * HEDGE;
#pragma unroll
        for (int j = 0; j < HEDGE; j++) {
            h0a[j] += o00 * w0[j] + o01 * w1[j];
            h1a[j] += o10 * w0[j] + o11 * w1[j];
        }
    }

#pragma unroll
    for (int j = 0; j < HEDGE; j++) {
        h0a[j] += __shfl_xor_sync(0xffffffffu, h0a[j], 1);
        h0a[j] += __shfl_xor_sync(0xffffffffu, h0a[j], 2);
        h1a[j] += __shfl_xor_sync(0xffffffffu, h1a[j], 1);
        h1a[j] += __shfl_xor_sync(0xffffffffu, h1a[j], 2);
    }

    __syncthreads();   // A planes dead -> alias gate partials

    if (tID == 0) {
        float* dst = (colhalf ? sH1 : sH0);
#pragma unroll
        for (int j = 0; j < HEDGE; j++) {
            dst[(m0 + gID) * HEDGE + j]     = h0a[j];
            dst[(m0 + gID + 8) * HEDGE + j] = h1a[j];
        }
    }
    __syncthreads();

    if (tid < MTILE) {
        int gr = nb + tid;
        if (gr < n) {
            float z = b2[0];
#pragma unroll
            for (int j = 0; j < HEDGE; j++) {
                float hv = sH0[tid * HEDGE + j] + sH1[tid * HEDGE + j] + sb1[j];
                hv = hv > 0.0f ? hv : 0.1f * hv;       // leaky_relu(0.1)
                z += hv * sW2[j];
            }
            float wd = 1.0f / (1.0f + expf(-z));
            g_s[gr] = log1pf(expf(4.0f * (wd - 0.5f)));
        }
    }
}

// ---------------------------------------------------------------------------
// K2: edge scatter (push). One warp per edge; red.global.add.v4.f32.
// Unchanged (proven ~112us).
// ---------------------------------------------------------------------------
__global__ void edge_kernel(const int* __restrict__ ei,
                            const float* __restrict__ ew,
                            float* __restrict__ out,
                            int E, int n) {
    int wid  = (blockIdx.x * blockDim.x + threadIdx.x) >> 5;
    int lane = threadIdx.x & 31;
    if (wid >= E) return;

    int src = ei[wid];
    int dst = ei[(size_t)E + wid];
    if ((unsigned)src >= (unsigned)n || (unsigned)dst >= (unsigned)n) return;

    float w = ew[wid] * g_s[src];
    w = fminf(fmaxf(w, 0.0f), 5.0f);                   // clip to [0, EW_MAX]

    float4 v = *(const float4*)(g_xp + (size_t)src * 128 + lane * 4);
    float* o = out + (size_t)dst * 128 + lane * 4;
    asm volatile("red.global.add.v4.f32 [%0], {%1, %2, %3, %4};"
                 :: "l"(o), "f"(w * v.x), "f"(w * v.y), "f"(w * v.z), "f"(w * v.w)
                 : "memory");
    if (lane == 0) atomicAdd(&g_deg[dst], fabsf(w));
}

// ---------------------------------------------------------------------------
// K3: finalize: gelu(out/(deg+eps) + x_proj), float4-vectorized — unchanged.
// ---------------------------------------------------------------------------
__global__ void finalize_kernel(float4* __restrict__ out4, int n) {
    int i = blockIdx.x * blockDim.x + threadIdx.x;
    int total4 = n * 32;
    if (i >= total4) return;
    int nid = i >> 5;
    float inv = 1.0f / (g_deg[nid] + 1e-6f);
    float4 a = out4[i];
    float4 p = ((const float4*)g_xp)[i];
    float v0 = a.x * inv + p.x;
    float v1 = a.y * inv + p.y;
    float v2 = a.z * inv + p.z;
    float v3 = a.w * inv + p.w;
    const float is2 = 0.70710678118654752f;
    float4 r;
    r.x = 0.5f * v0 * (1.0f + erff(v0 * is2));
    r.y = 0.5f * v1 * (1.0f + erff(v1 * is2));
    r.z = 0.5f * v2 * (1.0f + erff(v2 * is2));
    r.w = 0.5f * v3 * (1.0f + erff(v3 * is2));
    out4[i] = r;
}

// ---------------------------------------------------------------------------
extern "C" void kernel_launch(void* const* d_in, const int* in_sizes, int n_in,
                              void* d_out, int out_size) {
    const float* x     = (const float*)d_in[0];
    const float* state = (const float*)d_in[1];
    const int*   ei    = (const int*)d_in[2];
    const float* ew    = (const float*)d_in[3];
    const float* Win   = (const float*)d_in[4];
    const float* bin   = (const float*)d_in[5];
    const float* W1    = (const float*)d_in[6];
    const float* b1    = (const float*)d_in[7];
    const float* W2    = (const float*)d_in[8];
    const float* b2    = (const float*)d_in[9];

    int n = in_sizes[0] / 128;     // 50000
    int E = in_sizes[3];           // 800000
    float* out = (float*)d_out;

    static bool attr_set = false;
    if (!attr_set) {
        cudaFuncSetAttribute(proj_mma_kernel,
                             cudaFuncAttributeMaxDynamicSharedMemorySize, SM_TOTAL);
        attr_set = true;
    }

    prep_kernel<<<2048, 256>>>(Win, (float4*)out, out_size / 4, n);
    proj_mma_kernel<<<(n + MTILE - 1) / MTILE, 512, SM_TOTAL>>>(
        x, state, bin, W1, b1, W2, b2, n);

    int edge_blocks = (int)(((long long)E * 32 + 255) / 256);
    edge_kernel<<<edge_blocks, 256>>>(ei, ew, out, E, n);

    finalize_kernel<<<(n * 32 + 255) / 256, 256>>>((float4*)out, n);
}

// round 10
// speedup vs baseline: 2.0563x; 1.2672x over previous
#include <cuda_runtime.h>
#include <cuda_bf16.h>
#include <math.h>

// Problem constants: N=50000, E=800000, D_IN=256, D_OUT=128, H=16
#define NMAX   50000
#define EMAX   800000
#define DOUT   128
#define DIN    256
#define HEDGE  16

#define MTILE  128     // nodes per CTA in proj_mma
#define PAW    132     // A plane pitch in 32-bit words
#define P_B    24      // B chunk pitch in bf16

// Scratch (device globals: allocation-free per harness rules)
__device__ float g_xp[NMAX * DOUT];            // x_proj, 25.6 MB (L2-resident)
__device__ float g_s[NMAX];                    // per-node gate
__device__ __nv_bfloat16 g_Wt_hi[DOUT * DIN];  // W_in^T hi plane [n][k]
__device__ __nv_bfloat16 g_Wt_lo[DOUT * DIN];  // W_in^T lo plane [n][k]
// CSR (dst-sorted edges)
__device__ int   g_cnt[NMAX];
__device__ int   g_off[NMAX + 1];
__device__ int   g_cur[NMAX];
__device__ int   g_csr_src[EMAX];
__device__ float g_csr_ew[EMAX];
__device__ int   g_bsum[64];
__device__ int   g_boff[64];

// ---------------------------------------------------------------------------
__device__ __forceinline__ void split2(float f0, float f1, unsigned& hi, unsigned& lo) {
    asm("cvt.rn.bf16x2.f32 %0, %1, %2;" : "=r"(hi) : "f"(f1), "f"(f0));
    float h0 = __uint_as_float(hi << 16);
    float h1 = __uint_as_float(hi & 0xffff0000u);
    float r0 = f0 - h0;                   // exact (Sterbenz)
    float r1 = f1 - h1;
    asm("cvt.rn.bf16x2.f32 %0, %1, %2;" : "=r"(lo) : "f"(r1), "f"(r0));
}

__device__ __forceinline__ void mma_bf16(float c[4], const unsigned a[4],
                                         unsigned b0, unsigned b1) {
    asm("mma.sync.aligned.m16n8k16.row.col.f32.bf16.bf16.f32 "
        "{%0,%1,%2,%3}, {%4,%5,%6,%7}, {%8,%9}, {%0,%1,%2,%3};"
        : "+f"(c[0]), "+f"(c[1]), "+f"(c[2]), "+f"(c[3])
        : "r"(a[0]), "r"(a[1]), "r"(a[2]), "r"(a[3]), "r"(b0), "r"(b1));
}

// ---------------------------------------------------------------------------
// SMEM layout (bytes) for proj
// ---------------------------------------------------------------------------
#define SM_AHI   0
#define SM_ALO   67584
#define SM_B0H   135168
#define SM_B0L   141312
#define SM_B1H   147456
#define SM_B1L   153600
#define SM_W1    159744
#define SM_W2    167936
#define SM_B1V   168000
#define SM_BIN   168064
#define SM_TOTAL 168576

// ---------------------------------------------------------------------------
// K0: prep — split/transpose W_in to bf16 planes, zero CSR counters,
// and histogram dst (fused; all independent of proj outputs).
// ---------------------------------------------------------------------------
__global__ void prep_hist_kernel(const float* __restrict__ Win,
                                 const int* __restrict__ ei,
                                 int E, int n) {
    int i = blockIdx.x * blockDim.x + threadIdx.x;
    int stride = gridDim.x * blockDim.x;
    for (int j = i; j < n; j += stride) g_cnt[j] = 0;
    for (int j = i; j < DIN * DOUT; j += stride) {
        int k  = j >> 7;
        int nn = j & 127;
        float w = Win[j];
        __nv_bfloat16 h = __float2bfloat16_rn(w);
        __nv_bfloat16 l = __float2bfloat16_rn(w - __bfloat162float(h));
        g_Wt_hi[nn * DIN + k] = h;
        g_Wt_lo[nn * DIN + k] = l;
    }
}

__global__ void hist_kernel(const int* __restrict__ ei, int E, int n) {
    int e = blockIdx.x * blockDim.x + threadIdx.x;
    if (e >= E) return;
    int dst = ei[(size_t)E + e];
    if ((unsigned)dst < (unsigned)n) atomicAdd(&g_cnt[dst], 1);
}

// ---------------------------------------------------------------------------
// scan (3-phase, validated in R5)
// ---------------------------------------------------------------------------
__global__ void scan1_kernel(int n) {       // blockDim = 1024
    __shared__ int s[1024];
    int i = blockIdx.x * 1024 + threadIdx.x;
    int v = (i < n) ? g_cnt[i] : 0;
    s[threadIdx.x] = v;
    __syncthreads();
#pragma unroll
    for (int d = 1; d < 1024; d <<= 1) {
        int t = (threadIdx.x >= d) ? s[threadIdx.x - d] : 0;
        __syncthreads();
        s[threadIdx.x] += t;
        __syncthreads();
    }
    if (i < n) g_off[i] = s[threadIdx.x] - v;          // exclusive within block
    if (threadIdx.x == 1023) g_bsum[blockIdx.x] = s[1023];
}

__global__ void scan2_kernel(int nblk) {    // 1 block, 64 threads
    __shared__ int s[64];
    int v = (threadIdx.x < nblk) ? g_bsum[threadIdx.x] : 0;
    s[threadIdx.x] = v;
    __syncthreads();
#pragma unroll
    for (int d = 1; d < 64; d <<= 1) {
        int t = (threadIdx.x >= d) ? s[threadIdx.x - d] : 0;
        __syncthreads();
        s[threadIdx.x] += t;
        __syncthreads();
    }
    g_boff[threadIdx.x] = s[threadIdx.x] - v;          // exclusive
}

__global__ void scan3_kernel(int n) {
    int i = blockIdx.x * blockDim.x + threadIdx.x;
    if (i >= n) return;
    int o = g_off[i] + g_boff[i >> 10];
    g_off[i] = o;
    g_cur[i] = o;
    if (i == n - 1) g_off[n] = o + g_cnt[i];
}

// ---------------------------------------------------------------------------
// scatter: materialize dst-sorted (src, ew) records
// ---------------------------------------------------------------------------
__global__ void scatter_kernel(const int* __restrict__ ei,
                               const float* __restrict__ ew,
                               int E, int n) {
    int e = blockIdx.x * blockDim.x + threadIdx.x;
    if (e >= E) return;
    int dst = ei[(size_t)E + e];
    if ((unsigned)dst >= (unsigned)n) return;
    int src = ei[e];
    int pos = atomicAdd(&g_cur[dst], 1);
    g_csr_src[pos] = ((unsigned)src < (unsigned)n) ? src : -1;
    g_csr_ew[pos]  = ew[e];
}

// ---------------------------------------------------------------------------
// K1: proj via bf16 mma.sync (3-term split) + fused gate MLP. Unchanged (R9).
// ---------------------------------------------------------------------------
__global__ void __launch_bounds__(512, 1)
proj_mma_kernel(const float* __restrict__ x,
                const float* __restrict__ state,
                const float* __restrict__ bin,
                const float* __restrict__ W1,
                const float* __restrict__ b1,
                const float* __restrict__ W2,
                const float* __restrict__ b2,
                int n) {
    extern __shared__ char smem[];
    unsigned* sAhi = (unsigned*)(smem + SM_AHI);
    unsigned* sAlo = (unsigned*)(smem + SM_ALO);
    float* sW1 = (float*)(smem + SM_W1);
    float* sW2 = (float*)(smem + SM_W2);
    float* sb1 = (float*)(smem + SM_B1V);
    float* sBN = (float*)(smem + SM_BIN);
    float* sH0 = (float*)(smem + SM_AHI);
    float* sH1 = sH0 + MTILE * HEDGE;

    const int tid     = threadIdx.x;
    const int warp    = tid >> 5;
    const int lane    = tid & 31;
    const int gID     = lane >> 2;
    const int tID     = lane & 3;
    const int rowgrp  = warp & 7;
    const int colhalf = warp >> 3;
    const int nb      = blockIdx.x * MTILE;
    const int m0      = rowgrp * 16;
    const int cbase   = colhalf * 64;

    {
        int r = tid >> 2;
        int q = tid & 3;
        int gn = nb + r;
        bool valid = (gn < n);
        const float4* src = (q < 2)
            ? (const float4*)(x + (size_t)(valid ? gn : 0) * 128) + (q & 1) * 16
            : (const float4*)(state + (size_t)(valid ? gn : 0) * 128) + (q & 1) * 16;
        unsigned base = r * PAW + q * 32;
#pragma unroll
        for (int j = 0; j < 16; j++) {
            float4 v = valid ? src[j] : make_float4(0.f, 0.f, 0.f, 0.f);
            unsigned h0, l0, h1, l1;
            split2(v.x, v.y, h0, l0);
            split2(v.z, v.w, h1, l1);
            sAhi[base + 2 * j]     = h0;
            sAhi[base + 2 * j + 1] = h1;
            sAlo[base + 2 * j]     = l0;
            sAlo[base + 2 * j + 1] = l1;
        }
    }
    for (int i = tid; i < DOUT * HEDGE; i += 512) sW1[i] = W1[i];
    if (tid < HEDGE) {
        sW2[tid] = W2[tid];
        sb1[tid] = b1[tid];
    }
    if (tid >= 512 - DOUT) sBN[tid - (512 - DOUT)] = bin[tid - (512 - DOUT)];

    const int bplane = tid >> 8;
    const int brow   = (tid >> 1) & 127;
    const int bhalf  = tid & 1;
    const __nv_bfloat16* gsrc =
        (bplane ? g_Wt_lo : g_Wt_hi) + brow * DIN + bhalf * 8;
    char* sBd0 = smem + (bplane ? SM_B0L : SM_B0H) + brow * (P_B * 2) + bhalf * 16;
    char* sBd1 = smem + (bplane ? SM_B1L : SM_B1H) + brow * (P_B * 2) + bhalf * 16;

    *(uint4*)sBd0 = *(const uint4*)(gsrc);
    uint4 pf = *(const uint4*)(gsrc + 16);
    __syncthreads();

    float c[8][4];
#pragma unroll
    for (int nt = 0; nt < 8; nt++)
#pragma unroll
        for (int j = 0; j < 4; j++) c[nt][j] = 0.0f;

    for (int kc = 0; kc < 16; kc++) {
        if (kc < 15) {
            *(uint4*)(((kc & 1) == 0) ? sBd1 : sBd0) = pf;
            if (kc < 14) pf = *(const uint4*)(gsrc + (kc + 2) * 16);
        }

        unsigned ah[4], al[4];
        {
            unsigned w0 = (m0 + gID) * PAW + kc * 8 + tID;
            unsigned w1 = w0 + 8 * PAW;
            ah[0] = sAhi[w0];     al[0] = sAlo[w0];
            ah[1] = sAhi[w1];     al[1] = sAlo[w1];
            ah[2] = sAhi[w0 + 4]; al[2] = sAlo[w0 + 4];
            ah[3] = sAhi[w1 + 4]; al[3] = sAlo[w1 + 4];
        }

        const __nv_bfloat16* bH = (const __nv_bfloat16*)
            (smem + ((kc & 1) ? SM_B1H : SM_B0H));
        const __nv_bfloat16* bL = (const __nv_bfloat16*)
            (smem + ((kc & 1) ? SM_B1L : SM_B0L));

#pragma unroll
        for (int nt = 0; nt < 8; nt++) {
            const __nv_bfloat16* ph = bH + (cbase + nt * 8 + gID) * P_B + tID * 2;
            const __nv_bfloat16* pl = bL + (cbase + nt * 8 + gID) * P_B + tID * 2;
            unsigned bh0 = *(const unsigned*)(ph);
            unsigned bh1 = *(const unsigned*)(ph + 8);
            unsigned bl0 = *(const unsigned*)(pl);
            unsigned bl1 = *(const unsigned*)(pl + 8);
            mma_bf16(c[nt], ah, bh0, bh1);
            mma_bf16(c[nt], ah, bl0, bl1);
            mma_bf16(c[nt], al, bh0, bh1);
        }
        __syncthreads();
    }

    int r0 = nb + m0 + gID;
    int r1 = r0 + 8;

    float h0a[HEDGE], h1a[HEDGE];
#pragma unroll
    for (int j = 0; j < HEDGE; j++) { h0a[j] = 0.0f; h1a[j] = 0.0f; }

#pragma unroll
    for (int nt = 0; nt < 8; nt++) {
        int col = cbase + nt * 8 + tID * 2;
        float2 bv = make_float2(sBN[col], sBN[col + 1]);
        float o00 = c[nt][0] + bv.x, o01 = c[nt][1] + bv.y;
        float o10 = c[nt][2] + bv.x, o11 = c[nt][3] + bv.y;
        if (r0 < n) *(float2*)(g_xp + (size_t)r0 * 128 + col) = make_float2(o00, o01);
        if (r1 < n) *(float2*)(g_xp + (size_t)r1 * 128 + col) = make_float2(o10, o11);
        const float* w0 = sW1 + col * HEDGE;
        const float* w1 = sW1 + (col + 1) * HEDGE;
#pragma unroll
        for (int j = 0; j < HEDGE; j++) {
            h0a[j] += o00 * w0[j] + o01 * w1[j];
            h1a[j] += o10 * w0[j] + o11 * w1[j];
        }
    }

#pragma unroll
    for (int j = 0; j < HEDGE; j++) {
        h0a[j] += __shfl_xor_sync(0xffffffffu, h0a[j], 1);
        h0a[j] += __shfl_xor_sync(0xffffffffu, h0a[j], 2);
        h1a[j] += __shfl_xor_sync(0xffffffffu, h1a[j], 1);
        h1a[j] += __shfl_xor_sync(0xffffffffu, h1a[j], 2);
    }

    __syncthreads();

    if (tID == 0) {
        float* dst = (colhalf ? sH1 : sH0);
#pragma unroll
        for (int j = 0; j < HEDGE; j++) {
            dst[(m0 + gID) * HEDGE + j]     = h0a[j];
            dst[(m0 + gID + 8) * HEDGE + j] = h1a[j];
        }
    }
    __syncthreads();

    if (tid < MTILE) {
        int gr = nb + tid;
        if (gr < n) {
            float z = b2[0];
#pragma unroll
            for (int j = 0; j < HEDGE; j++) {
                float hv = sH0[tid * HEDGE + j] + sH1[tid * HEDGE + j] + sb1[j];
                hv = hv > 0.0f ? hv : 0.1f * hv;       // leaky_relu(0.1)
                z += hv * sW2[j];
            }
            float wd = 1.0f / (1.0f + expf(-z));
            g_s[gr] = log1pf(expf(4.0f * (wd - 0.5f)));
        }
    }
}

// ---------------------------------------------------------------------------
// K2: pull aggregation v2 + fused finalize. Warp per dst node, atomic-free.
// Phase 1: lanes resolve (src, w) for up to 32 edges IN PARALLEL.
// Phase 2: shfl-broadcast + independent coalesced row gathers (high MLP).
// out[nid] = gelu( (sum w*xp[src]) / (sum |w| + eps) + xp[nid] ), one store.
// ---------------------------------------------------------------------------
__global__ void pull_kernel(float* __restrict__ out, int n) {
    int nid  = (blockIdx.x * blockDim.x + threadIdx.x) >> 5;
    int lane = threadIdx.x & 31;
    if (nid >= n) return;

    const int beg = g_off[nid];
    const int end = g_off[nid + 1];

    float4 acc = make_float4(0.f, 0.f, 0.f, 0.f);
    float  sw  = 0.0f;
    const float4* xp4 = (const float4*)g_xp;

    for (int base = beg; base < end; base += 32) {
        int cnt = end - base;
        if (cnt > 32) cnt = 32;

        // phase 1: parallel resolve
        int   s = 0;
        float w = 0.0f;
        if (lane < cnt) {
            int sv = g_csr_src[base + lane];
            if (sv >= 0) {
                float e = g_csr_ew[base + lane];
                w = e * g_s[sv];
                w = fminf(fmaxf(w, 0.0f), 5.0f);
                s = sv;
            }
        }

        // phase 2: broadcast + gather (independent loads, unrolled)
#pragma unroll 4
        for (int j = 0; j < cnt; j++) {
            int   sj = __shfl_sync(0xffffffffu, s, j);
            float wj = __shfl_sync(0xffffffffu, w, j);
            float4 v = xp4[(size_t)sj * 32 + lane];
            acc.x += wj * v.x;
            acc.y += wj * v.y;
            acc.z += wj * v.z;
            acc.w += wj * v.w;
            sw += wj;                      // w >= 0 after clip -> |w| == w
        }
    }

    float inv = 1.0f / (sw + 1e-6f);
    float4 p  = xp4[(size_t)nid * 32 + lane];
    float v0 = acc.x * inv + p.x;
    float v1 = acc.y * inv + p.y;
    float v2 = acc.z * inv + p.z;
    float v3 = acc.w * inv + p.w;
    const float is2 = 0.70710678118654752f;
    float4 r;
    r.x = 0.5f * v0 * (1.0f + erff(v0 * is2));
    r.y = 0.5f * v1 * (1.0f + erff(v1 * is2));
    r.z = 0.5f * v2 * (1.0f + erff(v2 * is2));
    r.w = 0.5f * v3 * (1.0f + erff(v3 * is2));
    ((float4*)out)[(size_t)nid * 32 + lane] = r;
}

// ---------------------------------------------------------------------------
extern "C" void kernel_launch(void* const* d_in, const int* in_sizes, int n_in,
                              void* d_out, int out_size) {
    const float* x     = (const float*)d_in[0];
    const float* state = (const float*)d_in[1];
    const int*   ei    = (const int*)d_in[2];
    const float* ew    = (const float*)d_in[3];
    const float* Win   = (const float*)d_in[4];
    const float* bin   = (const float*)d_in[5];
    const float* W1    = (const float*)d_in[6];
    const float* b1    = (const float*)d_in[7];
    const float* W2    = (const float*)d_in[8];
    const float* b2    = (const float*)d_in[9];

    int n = in_sizes[0] / 128;     // 50000
    int E = in_sizes[3];           // 800000
    float* out = (float*)d_out;

    static bool attr_set = false;
    if (!attr_set) {
        cudaFuncSetAttribute(proj_mma_kernel,
                             cudaFuncAttributeMaxDynamicSharedMemorySize, SM_TOTAL);
        attr_set = true;
    }

    int nblk = (n + 1023) / 1024;

    // CSR build (independent of proj outputs)
    prep_hist_kernel<<<512, 256>>>(Win, ei, E, n);
    hist_kernel<<<(E + 255) / 256, 256>>>(ei, E, n);
    scan1_kernel<<<nblk, 1024>>>(n);
    scan2_kernel<<<1, 64>>>(nblk);
    scan3_kernel<<<(n + 255) / 256, 256>>>(n);
    scatter_kernel<<<(E + 255) / 256, 256>>>(ei, ew, E, n);

    // node projection + fused gate
    proj_mma_kernel<<<(n + MTILE - 1) / MTILE, 512, SM_TOTAL>>>(
        x, state, bin, W1, b1, W2, b2, n);

    // pull aggregation + fused finalize (single d_out write, no zeroing)
    pull_kernel<<<(n * 32 + 255) / 256, 256>>>(out, n);
}